// round 1
// baseline (speedup 1.0000x reference)
#include <cuda_runtime.h>
#include <cuda_bf16.h>
#include <cstdint>

// Problem constants (from reference): B=16, T=4096 -> N=65536 tokens, D=64, K=1024
#define D 64
#define K 1024
#define BM 128   // tokens per block tile
#define BK 128   // codes per chunk
#define TM 8     // tokens per thread
#define TN 8     // codes per thread

// Scratch (no cudaMalloc allowed): transposed codebook + per-code squared norms
__device__ float g_embedT[K * D];   // [k][d]
__device__ float g_ekk[K];          // ||e_k||^2

// ---------------- f32x2 packed helpers ----------------
typedef unsigned long long ull;

__device__ __forceinline__ ull ffma2(ull a, ull b, ull c) {
    ull d_;
    asm("fma.rn.f32x2 %0, %1, %2, %3;" : "=l"(d_) : "l"(a), "l"(b), "l"(c));
    return d_;
}
__device__ __forceinline__ ull dup_f32(float x) {
    ull r;
    asm("mov.b64 %0, {%1, %1};" : "=l"(r) : "f"(x));
    return r;
}
__device__ __forceinline__ float2 unpack_f32x2(ull a) {
    float2 u;
    asm("mov.b64 {%0, %1}, %2;" : "=f"(u.x), "=f"(u.y) : "l"(a));
    return u;
}

// ---------------- prep: transpose codebook + code norms ----------------
__global__ void vq_prep(const float* __restrict__ embed) {
    int i = blockIdx.x * blockDim.x + threadIdx.x;
    if (i < K * D) {
        int k = i >> 6;       // i / 64
        int d = i & 63;       // i % 64
        g_embedT[i] = embed[d * K + k];
    }
    if (i < K) {
        float s = 0.f;
        #pragma unroll
        for (int d = 0; d < D; d++) {
            float v = embed[d * K + i];   // coalesced across i
            s = fmaf(v, v, s);
        }
        g_ekk[i] = s;
    }
}

// ---------------- main: fused distance GEMM + argmin + gather ----------------
__global__ __launch_bounds__(256, 2)
void vq_main(const float* __restrict__ input,
             const float* __restrict__ embed,
             float* __restrict__ q_out,
             float* __restrict__ diff_out,
             float* __restrict__ ind_out) {
    extern __shared__ float smem[];
    float* xs = smem;                        // [D][BM]  = 8192 floats
    float* es = smem + D * BM;               // [D][BK]  = 8192 floats
    int*   best_sm = (int*)(smem + 2 * D * BM);  // [BM]

    const int tid = threadIdx.x;
    const int tx  = tid & 15;     // code dimension (16 threads cover 128 codes)
    const int ty  = tid >> 4;     // token dimension (16 threads cover 128 tokens)
    const int n0  = blockIdx.x * BM;

    // ---- load x tile, transposed to [d][token] ----
    const float4* in4 = reinterpret_cast<const float4*>(input + (size_t)n0 * D);
    #pragma unroll
    for (int t = tid; t < BM * D / 4; t += 256) {
        float4 v = in4[t];                 // fully coalesced
        int row = t >> 4;                  // token in tile
        int c   = (t & 15) << 2;           // starting d
        xs[(c + 0) * BM + row] = v.x;
        xs[(c + 1) * BM + row] = v.y;
        xs[(c + 2) * BM + row] = v.z;
        xs[(c + 3) * BM + row] = v.w;
    }

    float best_s[TM];
    int   best_i[TM];
    #pragma unroll
    for (int i = 0; i < TM; i++) { best_s[i] = 3.4e38f; best_i[i] = 0; }

    for (int kb = 0; kb < K; kb += BK) {
        __syncthreads();   // previous compute done (and x tile ready on iter 0 via next sync)
        // ---- load e chunk [d][k_local] ----
        #pragma unroll
        for (int t = tid; t < D * BK / 4; t += 256) {
            int d = t >> 5;          // 32 float4 per row
            int c = (t & 31) << 2;
            *reinterpret_cast<float4*>(&es[d * BK + c]) =
                *reinterpret_cast<const float4*>(&embed[(size_t)d * K + kb + c]);
        }
        __syncthreads();

        // ---- 8x8 micro-tile dot products, packed f32x2 ----
        ull acc[TM][4];
        #pragma unroll
        for (int i = 0; i < TM; i++)
            #pragma unroll
            for (int j = 0; j < 4; j++) acc[i][j] = 0ULL;

        #pragma unroll 4
        for (int d = 0; d < D; d++) {
            float4 xa = *reinterpret_cast<const float4*>(&xs[d * BM + ty * TM]);
            float4 xb = *reinterpret_cast<const float4*>(&xs[d * BM + ty * TM + 4]);
            ulonglong2 e0 = *reinterpret_cast<const ulonglong2*>(&es[d * BK + tx * TN]);
            ulonglong2 e1 = *reinterpret_cast<const ulonglong2*>(&es[d * BK + tx * TN + 4]);

            ull xd[TM];
            xd[0] = dup_f32(xa.x); xd[1] = dup_f32(xa.y);
            xd[2] = dup_f32(xa.z); xd[3] = dup_f32(xa.w);
            xd[4] = dup_f32(xb.x); xd[5] = dup_f32(xb.y);
            xd[6] = dup_f32(xb.z); xd[7] = dup_f32(xb.w);

            #pragma unroll
            for (int i = 0; i < TM; i++) {
                acc[i][0] = ffma2(xd[i], e0.x, acc[i][0]);
                acc[i][1] = ffma2(xd[i], e0.y, acc[i][1]);
                acc[i][2] = ffma2(xd[i], e1.x, acc[i][2]);
                acc[i][3] = ffma2(xd[i], e1.y, acc[i][3]);
            }
        }

        // ---- scores and running argmin (ascending k keeps lowest-index tie) ----
        #pragma unroll
        for (int i = 0; i < TM; i++) {
            #pragma unroll
            for (int j2 = 0; j2 < 4; j2++) {
                float2 dp = unpack_f32x2(acc[i][j2]);
                int k0 = kb + tx * TN + j2 * 2;
                float s0 = fmaf(-2.f, dp.x, __ldg(&g_ekk[k0]));
                float s1 = fmaf(-2.f, dp.y, __ldg(&g_ekk[k0 + 1]));
                if (s0 < best_s[i]) { best_s[i] = s0; best_i[i] = k0; }
                if (s1 < best_s[i]) { best_s[i] = s1; best_i[i] = k0 + 1; }
            }
        }
    }

    // ---- reduce across the 16 tx-lanes (half-warp groups; xor<=8 stays inside) ----
    #pragma unroll
    for (int i = 0; i < TM; i++) {
        float s = best_s[i];
        int   bi = best_i[i];
        #pragma unroll
        for (int m = 8; m >= 1; m >>= 1) {
            float so = __shfl_xor_sync(0xffffffffu, s, m);
            int   io = __shfl_xor_sync(0xffffffffu, bi, m);
            if (so < s || (so == s && io < bi)) { s = so; bi = io; }
        }
        if (tx == 0) {
            int row = ty * TM + i;
            best_sm[row] = bi;
            if (ind_out) ind_out[n0 + row] = (float)bi;
        }
    }
    __syncthreads();

    // ---- gather quantize + diff, coalesced float4 writes ----
    #pragma unroll
    for (int t = tid; t < BM * (D / 4); t += 256) {
        int row = t >> 4;
        int c   = (t & 15) << 2;
        int kb_ = best_sm[row];
        float4 q = *reinterpret_cast<const float4*>(&g_embedT[kb_ * D + c]);
        float x0 = xs[(c + 0) * BM + row];
        float x1 = xs[(c + 1) * BM + row];
        float x2 = xs[(c + 2) * BM + row];
        float x3 = xs[(c + 3) * BM + row];
        size_t o = (size_t)(n0 + row) * D + c;
        *reinterpret_cast<float4*>(&q_out[o]) = q;
        if (diff_out) {
            float4 df;
            df.x = (q.x - x0) * (q.x - x0);
            df.y = (q.y - x1) * (q.y - x1);
            df.z = (q.z - x2) * (q.z - x2);
            df.w = (q.w - x3) * (q.w - x3);
            *reinterpret_cast<float4*>(&diff_out[o]) = df;
        }
    }
}

#define SMEM_BYTES ((2 * D * BM) * 4 + BM * 4)

extern "C" void kernel_launch(void* const* d_in, const int* in_sizes, int n_in,
                              void* d_out, int out_size) {
    const float* input = (const float*)d_in[0];   // [B,T,D] fp32
    const float* embed = (const float*)d_in[1];   // [D,K]   fp32

    const int N = in_sizes[0] / D;                // 65536 tokens
    const long nd = (long)N * D;

    float* out = (float*)d_out;
    float* q_out    = out;
    float* diff_out = nullptr;
    float* ind_out  = nullptr;
    if ((long)out_size >= 2 * nd + N) { diff_out = out + nd; ind_out = out + 2 * nd; }
    else if ((long)out_size >= 2 * nd) { diff_out = out + nd; }

    cudaFuncSetAttribute(vq_main, cudaFuncAttributeMaxDynamicSharedMemorySize, SMEM_BYTES);

    vq_prep<<<(K * D + 255) / 256, 256>>>(embed);
    vq_main<<<N / BM, 256, SMEM_BYTES>>>(input, embed, q_out, diff_out, ind_out);
}

// round 2
// speedup vs baseline: 1.0327x; 1.0327x over previous
#include <cuda_runtime.h>
#include <cuda_bf16.h>
#include <cstdint>

// B=16, T=4096 -> N=65536 tokens, D=64, K=1024
#define D 64
#define K 1024
#define BM 128          // tokens per CTA
#define BK 64           // codes staged per chunk
#define NC (K / BK)     // 16 chunks
#define XPAD 130        // ull stride per d-row (even -> 16B-aligned LDS.128)
#define THREADS 128

__device__ float g_embedT[K * D];  // [k][d]
__device__ float g_h[K];           // 0.5 * ||e_k||^2

typedef unsigned long long ull;

__device__ __forceinline__ ull ffma2(ull a, ull b, ull c) {
    ull d_;
    asm("fma.rn.f32x2 %0, %1, %2, %3;" : "=l"(d_) : "l"(a), "l"(b), "l"(c));
    return d_;
}
__device__ __forceinline__ ull dup_f32(float x) {
    ull r;
    asm("mov.b64 %0, {%1, %1};" : "=l"(r) : "f"(x));
    return r;
}
__device__ __forceinline__ float2 unpack2(ull a) {
    float2 u;
    asm("mov.b64 {%0, %1}, %2;" : "=f"(u.x), "=f"(u.y) : "l"(a));
    return u;
}
__device__ __forceinline__ void cp16(uint32_t s, const void* g) {
    asm volatile("cp.async.cg.shared.global [%0], [%1], 16;" :: "r"(s), "l"(g));
}

// ---------------- prep: transpose codebook + half code norms ----------------
__global__ void vq_prep(const float* __restrict__ embed) {
    int i = blockIdx.x * blockDim.x + threadIdx.x;
    if (i < K * D) {
        int k = i >> 6;
        int d = i & 63;
        g_embedT[i] = embed[d * K + k];
    }
    if (i < K) {
        float s = 0.f;
        #pragma unroll
        for (int d = 0; d < D; d++) {
            float v = embed[d * K + i];
            s = fmaf(v, v, s);
        }
        g_h[i] = 0.5f * s;
    }
}

// ---------------- main: fused distance GEMM + argmin + gather ----------------
__global__ __launch_bounds__(THREADS)
void vq_main(const float* __restrict__ input,
             const float* __restrict__ embed,
             float* __restrict__ q_out,
             float* __restrict__ diff_out,
             float* __restrict__ ind_out) {
    extern __shared__ char smem_raw[];
    ull*   xs = (ull*)smem_raw;                                // [D][XPAD] duplicated x
    float* es = (float*)(smem_raw + (size_t)D * XPAD * 8);     // [2][D][BK]
    float* hs = es + 2 * D * BK;                               // [K]
    int*   best_sm = (int*)(hs + K);                           // [BM]

    const int tid = threadIdx.x;
    const int tx  = tid & 7;    // 8 thread-cols x TN=8 codes -> BK=64
    const int ty  = tid >> 3;   // 16 thread-rows x TM=8 tokens -> BM=128
    const int n0  = blockIdx.x * BM;

    // ---- prologue: x tile, coalesced read -> duplicated+transposed shared ----
    const float4* in4 = reinterpret_cast<const float4*>(input + (size_t)n0 * D);
    #pragma unroll
    for (int t = tid; t < BM * D / 4; t += THREADS) {
        float4 v = in4[t];
        int row = t >> 4;              // token in tile
        int c   = (t & 15) << 2;       // starting d
        xs[(c + 0) * XPAD + row] = dup_f32(v.x);
        xs[(c + 1) * XPAD + row] = dup_f32(v.y);
        xs[(c + 2) * XPAD + row] = dup_f32(v.z);
        xs[(c + 3) * XPAD + row] = dup_f32(v.w);
    }
    #pragma unroll
    for (int t = tid; t < K; t += THREADS) hs[t] = g_h[t];

    uint32_t es_s = (uint32_t)__cvta_generic_to_shared(es);

    // ---- prefetch chunk 0 (cp.async) ----
    #pragma unroll
    for (int i = 0; i < 8; i++) {
        int idx = i * THREADS + tid;
        int d = idx >> 4, c4 = (idx & 15) << 2;
        cp16(es_s + (uint32_t)(d * BK + c4) * 4, embed + (size_t)d * K + c4);
    }
    asm volatile("cp.async.commit_group;");

    float best_s[8];
    int   best_i[8];
    #pragma unroll
    for (int i = 0; i < 8; i++) { best_s[i] = 3.4e38f; best_i[i] = 0; }

    for (int ck = 0; ck < NC; ck++) {
        asm volatile("cp.async.wait_group 0;");
        __syncthreads();   // chunk ck visible; everyone done with chunk ck-1's buffer

        if (ck + 1 < NC) {
            int kb2 = (ck + 1) * BK;
            uint32_t dst = es_s + (uint32_t)(((ck + 1) & 1) * D * BK) * 4;
            #pragma unroll
            for (int i = 0; i < 8; i++) {
                int idx = i * THREADS + tid;
                int d = idx >> 4, c4 = (idx & 15) << 2;
                cp16(dst + (uint32_t)(d * BK + c4) * 4,
                     embed + (size_t)d * K + kb2 + c4);
            }
            asm volatile("cp.async.commit_group;");
        }

        const float* eb = es + (ck & 1) * D * BK;
        ull acc[8][4];
        #pragma unroll
        for (int i = 0; i < 8; i++) { acc[i][0] = acc[i][1] = acc[i][2] = acc[i][3] = 0ULL; }

        const ull* xrow = xs + ty * 8;
        const char* ebase = (const char*)(eb + tx * 8);

        #pragma unroll 8
        for (int d = 0; d < D; d++) {
            ulonglong2 x01 = *(const ulonglong2*)(xrow + d * XPAD + 0);
            ulonglong2 x23 = *(const ulonglong2*)(xrow + d * XPAD + 2);
            ulonglong2 x45 = *(const ulonglong2*)(xrow + d * XPAD + 4);
            ulonglong2 x67 = *(const ulonglong2*)(xrow + d * XPAD + 6);
            ulonglong2 e01 = *(const ulonglong2*)(ebase + d * BK * 4);
            ulonglong2 e23 = *(const ulonglong2*)(ebase + d * BK * 4 + 16);

            ull xv[8] = {x01.x, x01.y, x23.x, x23.y, x45.x, x45.y, x67.x, x67.y};
            #pragma unroll
            for (int i = 0; i < 8; i++) {
                acc[i][0] = ffma2(xv[i], e01.x, acc[i][0]);
                acc[i][1] = ffma2(xv[i], e01.y, acc[i][1]);
                acc[i][2] = ffma2(xv[i], e23.x, acc[i][2]);
                acc[i][3] = ffma2(xv[i], e23.y, acc[i][3]);
            }
        }

        // ---- scores + running argmin (ascending k keeps lowest-index tie) ----
        int kb = ck * BK;
        float4 hA = *(const float4*)(hs + kb + tx * 8);
        float4 hB = *(const float4*)(hs + kb + tx * 8 + 4);
        float hv[8] = {hA.x, hA.y, hA.z, hA.w, hB.x, hB.y, hB.z, hB.w};
        #pragma unroll
        for (int i = 0; i < 8; i++) {
            #pragma unroll
            for (int j = 0; j < 4; j++) {
                float2 p = unpack2(acc[i][j]);
                int k0 = kb + tx * 8 + j * 2;
                float s0 = hv[j * 2]     - p.x;
                float s1 = hv[j * 2 + 1] - p.y;
                if (s0 < best_s[i]) { best_s[i] = s0; best_i[i] = k0; }
                if (s1 < best_s[i]) { best_s[i] = s1; best_i[i] = k0 + 1; }
            }
        }
    }

    // ---- reduce across the 8 tx lanes ----
    #pragma unroll
    for (int i = 0; i < 8; i++) {
        float s = best_s[i];
        int   bi = best_i[i];
        #pragma unroll
        for (int m = 4; m >= 1; m >>= 1) {
            float so = __shfl_xor_sync(0xffffffffu, s, m);
            int   io = __shfl_xor_sync(0xffffffffu, bi, m);
            if (so < s || (so == s && io < bi)) { s = so; bi = io; }
        }
        if (tx == 0) {
            int row = ty * 8 + i;
            best_sm[row] = bi;
            if (ind_out) ind_out[n0 + row] = (float)bi;
        }
    }
    __syncthreads();

    // ---- gather quantize + diff, coalesced float4 writes ----
    #pragma unroll
    for (int t = tid; t < BM * D / 4; t += THREADS) {
        int row = t >> 4;
        int c   = (t & 15) << 2;
        int kq  = best_sm[row];
        float4 q = *(const float4*)(g_embedT + kq * D + c);
        float x0 = unpack2(xs[(c + 0) * XPAD + row]).x;
        float x1 = unpack2(xs[(c + 1) * XPAD + row]).x;
        float x2 = unpack2(xs[(c + 2) * XPAD + row]).x;
        float x3 = unpack2(xs[(c + 3) * XPAD + row]).x;
        size_t o = (size_t)(n0 + row) * D + c;
        *reinterpret_cast<float4*>(&q_out[o]) = q;
        if (diff_out) {
            float4 df;
            df.x = (q.x - x0) * (q.x - x0);
            df.y = (q.y - x1) * (q.y - x1);
            df.z = (q.z - x2) * (q.z - x2);
            df.w = (q.w - x3) * (q.w - x3);
            *reinterpret_cast<float4*>(&diff_out[o]) = df;
        }
    }
}

#define SMEM_BYTES ((size_t)D * XPAD * 8 + 2 * D * BK * 4 + K * 4 + BM * 4)

extern "C" void kernel_launch(void* const* d_in, const int* in_sizes, int n_in,
                              void* d_out, int out_size) {
    const float* input = (const float*)d_in[0];   // [B,T,D] fp32
    const float* embed = (const float*)d_in[1];   // [D,K]   fp32

    const int N = in_sizes[0] / D;
    const long nd = (long)N * D;

    float* out = (float*)d_out;
    float* q_out    = out;
    float* diff_out = nullptr;
    float* ind_out  = nullptr;
    if ((long)out_size >= 2 * nd + N) { diff_out = out + nd; ind_out = out + 2 * nd; }
    else if ((long)out_size >= 2 * nd) { diff_out = out + nd; }

    cudaFuncSetAttribute(vq_main, cudaFuncAttributeMaxDynamicSharedMemorySize, (int)SMEM_BYTES);

    vq_prep<<<(K * D + 255) / 256, 256>>>(embed);
    vq_main<<<N / BM, THREADS, SMEM_BYTES>>>(input, embed, q_out, diff_out, ind_out);
}